// round 14
// baseline (speedup 1.0000x reference)
#include <cuda_runtime.h>
#include <cuda_bf16.h>
#include <cuda_fp16.h>
#include <cstdint>

#define NV 50000
#define NE 10000
#define NP 800000
#define D  256
#define CAPE 192
#define CAPV 64

// ---------------- device scratch (no runtime allocation allowed) -----------
__device__ __half g_H[NV * D];                // 25.6 MB projected vertex features (fp16)
__device__ __half g_ef[NE * D];               // 5.1 MB  hyperedge features (fp16)
__device__ int    g_ecnt[NE];
__device__ int    g_vcnt[NV];
__device__ int    g_eslot[NE * CAPE];
__device__ int    g_vslot[NV * CAPV];
__device__ __half g_Wt16[D * D];              // W^T fp16 [n][k]

__device__ __forceinline__ uint32_t smem_u32(const void* p) {
    uint32_t a;
    asm("{ .reg .u64 t; cvta.to.shared.u64 t, %1; cvt.u32.u64 %0, t; }"
        : "=r"(a) : "l"(p));
    return a;
}

#define CP_ASYNC16(dst, src) \
    asm volatile("cp.async.cg.shared.global [%0], [%1], 16;" :: "r"(dst), "l"(src))
#define CP_COMMIT() asm volatile("cp.async.commit_group;" ::: "memory")
#define CP_WAIT0()  asm volatile("cp.async.wait_group 0;" ::: "memory")

// ---------------- init: zero counters + fp16-transpose W --------------------
__global__ void k_init(const float* __restrict__ W) {
    int i = blockIdx.x * blockDim.x + threadIdx.x;   // 65536 threads
    if (i < NE) g_ecnt[i] = 0;
    if (i < NV) g_vcnt[i] = 0;
    int k = i >> 8, n = i & 255;
    g_Wt16[n * D + k] = __float2half_rn(W[k * D + n]);
}

// ---------------- build inverted slot lists (2 pairs / thread) --------------
__global__ void k_build(const int* __restrict__ v_idx,
                        const int* __restrict__ e_idx) {
    int i = blockIdx.x * blockDim.x + threadIdx.x;
    if (i >= NP / 2) return;
    int2 vv = ((const int2*)v_idx)[i];
    int2 ee = ((const int2*)e_idx)[i];
#pragma unroll
    for (int t = 0; t < 2; t++) {
        int v = t ? vv.y : vv.x;
        int e = t ? ee.y : ee.x;
        int pe = atomicAdd(&g_ecnt[e], 1);
        if (pe < CAPE) g_eslot[e * CAPE + pe] = v;
        int pv = atomicAdd(&g_vcnt[v], 1);
        if (pv < CAPV) g_vslot[v * CAPV + pv] = e;
    }
}

// ---------------- fp16 GEMM (HMMA): H = X*W + b ------------------------------
// CTA tile 128x256, 512 threads / 16 warps (4 M x 4 N), warp tile 32x64.
// X fp32->fp16 converted in regs, double-buffered smem; W chunk double-buffered
// via cp.async. H ~= Xh*Wh (dropped X*Wl, Xl*W ~ 2.8e-4 each).
#define MT 128
#define KC 64
#define NTHR 512
#define SM_W 0                       // 2 x 32 KB
#define SM_X (64 * 1024)             // 2 x 16 KB
#define SMEM_BYTES (96 * 1024)

extern __shared__ __align__(1024) char dynsm[];

__global__ __launch_bounds__(NTHR, 1) void k_gemm(const float* __restrict__ X,
                                                  const float* __restrict__ bias) {
    char* sm = dynsm;
    const int tid  = threadIdx.x;
    const int wid  = tid >> 5;
    const int lane = tid & 31;
    const int mbase = blockIdx.x * MT;
    const int wm = wid & 3;          // 0..3 -> 32 M rows
    const int wn = wid >> 2;         // 0..3 -> 64 N cols

    const uint32_t sm_u = smem_u32(sm);
    const uint32_t xorv = (uint32_t)(lane & 7) << 4;

    uint32_t aoff[2], boff[4];
#pragma unroll
    for (int t = 0; t < 2; t++)
        aoff[t] = (uint32_t)((wm * 32 + t * 16 + (lane & 15)) * 128 + (lane >> 4) * 16);
#pragma unroll
    for (int jj = 0; jj < 4; jj++)
        boff[jj] = (uint32_t)((wn * 64 + jj * 16 + (lane & 15)) * 128 + (lane >> 4) * 16);

    float acc[2][8][4];
#pragma unroll
    for (int t = 0; t < 2; t++)
#pragma unroll
        for (int j = 0; j < 8; j++)
#pragma unroll
            for (int q = 0; q < 4; q++) acc[t][j][q] = 0.f;

    float4 pf[4];   // X prefetch: 2 (row,seg) assignments x 8 floats

#define LOADX(c) do {                                                          \
    int kc = (c) * KC;                                                         \
    _Pragma("unroll")                                                          \
    for (int u2 = 0; u2 < 2; u2++) {                                           \
        int a = tid + u2 * NTHR;                                               \
        int r = a >> 3, sg = a & 7;                                            \
        int gr = mbase + r;                                                    \
        if (gr < NV) {                                                         \
            const float* p = X + (size_t)gr * D + kc + sg * 8;                 \
            pf[2 * u2]     = *(const float4*)(p);                              \
            pf[2 * u2 + 1] = *(const float4*)(p + 4);                          \
        } else {                                                               \
            pf[2 * u2] = pf[2 * u2 + 1] = make_float4(0.f, 0.f, 0.f, 0.f);     \
        }                                                                      \
    } } while (0)

#define CONVX(b) do {                                                          \
    _Pragma("unroll")                                                          \
    for (int u2 = 0; u2 < 2; u2++) {                                           \
        int a = tid + u2 * NTHR;                                               \
        int r = a >> 3, sg = a & 7;                                            \
        uint32_t off = (uint32_t)(r * 128 + sg * 16);                          \
        uint32_t sw  = off ^ (uint32_t)((r & 7) << 4);                         \
        __half2 h0 = __floats2half2_rn(pf[2*u2].x,   pf[2*u2].y);              \
        __half2 h1 = __floats2half2_rn(pf[2*u2].z,   pf[2*u2].w);              \
        __half2 h2 = __floats2half2_rn(pf[2*u2+1].x, pf[2*u2+1].y);            \
        __half2 h3 = __floats2half2_rn(pf[2*u2+1].z, pf[2*u2+1].w);            \
        char* xb = sm + SM_X + (b) * 16384;                                    \
        *(uint4*)(xb + sw) = make_uint4(*(uint32_t*)&h0, *(uint32_t*)&h1,      \
                                        *(uint32_t*)&h2, *(uint32_t*)&h3);     \
    } } while (0)

#define CPW(c, b) do {                                                         \
    int kc = (c) * KC;                                                         \
    _Pragma("unroll")                                                          \
    for (int u = 0; u < 4; u++) {                                              \
        int a = tid + u * NTHR;                                                \
        int n = a >> 3, sg = a & 7;                                            \
        const __half* srcp = g_Wt16 + (size_t)n * D + kc + sg * 8;             \
        uint32_t dst = sm_u + SM_W + (uint32_t)((b) * 32768) +                 \
                       (uint32_t)(n * 128) +                                   \
                       ((uint32_t)(sg * 16) ^ ((uint32_t)(n & 7) << 4));       \
        CP_ASYNC16(dst, srcp);                                                 \
    } } while (0)

    // prologue: stage chunk 0
    LOADX(0);
    CPW(0, 0);
    CP_COMMIT();
    CONVX(0);
    CP_WAIT0();
    __syncthreads();

    for (int c = 0; c < 4; c++) {
        if (c < 3) {
            LOADX(c + 1);
            CPW(c + 1, (c + 1) & 1);
            CP_COMMIT();
        }
        const uint32_t xbase = sm_u + SM_X + (uint32_t)((c & 1) * 16384);
        const uint32_t wbase = sm_u + SM_W + (uint32_t)((c & 1) * 32768);
#pragma unroll
        for (int s = 0; s < 4; s++) {
            const uint32_t kb = (uint32_t)(s * 32);
            uint32_t ar[2][4], br[4][4];
#pragma unroll
            for (int t = 0; t < 2; t++) {
                uint32_t ah = xbase + ((aoff[t] + kb) ^ xorv);
                asm volatile(
                    "ldmatrix.sync.aligned.m8n8.x4.shared.b16 {%0,%1,%2,%3}, [%4];"
                    : "=r"(ar[t][0]), "=r"(ar[t][1]), "=r"(ar[t][2]), "=r"(ar[t][3])
                    : "r"(ah));
            }
#pragma unroll
            for (int jj = 0; jj < 4; jj++) {
                uint32_t bh = wbase + ((boff[jj] + kb) ^ xorv);
                asm volatile(
                    "ldmatrix.sync.aligned.m8n8.x4.shared.b16 {%0,%1,%2,%3}, [%4];"
                    : "=r"(br[jj][0]), "=r"(br[jj][1]), "=r"(br[jj][2]), "=r"(br[jj][3])
                    : "r"(bh));
            }
#pragma unroll
            for (int t = 0; t < 2; t++)
#pragma unroll
                for (int j = 0; j < 8; j++) {
                    const int u = j >> 1, h = j & 1;
                    asm volatile(
                        "mma.sync.aligned.m16n8k16.row.col.f32.f16.f16.f32 "
                        "{%0,%1,%2,%3}, {%4,%5,%6,%7}, {%8,%9}, {%0,%1,%2,%3};"
                        : "+f"(acc[t][j][0]), "+f"(acc[t][j][1]),
                          "+f"(acc[t][j][2]), "+f"(acc[t][j][3])
                        : "r"(ar[t][0]), "r"(ar[t][1]), "r"(ar[t][2]), "r"(ar[t][3]),
                          "r"(br[u][h]), "r"(br[u][2 + h]));
                }
        }
        if (c < 3) {
            CONVX((c + 1) & 1);
            CP_WAIT0();
            __syncthreads();
        }
    }

    // epilogue: C frags + bias -> g_H (fp16)
    const int r0 = lane >> 2;
    const int c2 = (lane & 3) * 2;
#pragma unroll
    for (int t = 0; t < 2; t++) {
        int row = mbase + wm * 32 + t * 16 + r0;
#pragma unroll
        for (int j = 0; j < 8; j++) {
            int col = wn * 64 + j * 8 + c2;
            float2 bv = *(const float2*)(bias + col);
            if (row < NV) {
                __half2 o = __floats2half2_rn(acc[t][j][0] + bv.x,
                                              acc[t][j][1] + bv.y);
                *(__half2*)(g_H + (size_t)row * D + col) = o;
            }
            if (row + 8 < NV) {
                __half2 o = __floats2half2_rn(acc[t][j][2] + bv.x,
                                              acc[t][j][3] + bv.y);
                *(__half2*)(g_H + (size_t)(row + 8) * D + col) = o;
            }
        }
    }
#undef LOADX
#undef CONVX
#undef CPW
}

// ---- helper: accumulate a half2-packed uint4 into 8 fp32 lanes --------------
__device__ __forceinline__ void acc_u4(float* acc, uint4 u) {
    float2 a = __half22float2(*(__half2*)&u.x);
    float2 b = __half22float2(*(__half2*)&u.y);
    float2 c = __half22float2(*(__half2*)&u.z);
    float2 d = __half22float2(*(__half2*)&u.w);
    acc[0] += a.x; acc[1] += a.y; acc[2] += b.x; acc[3] += b.y;
    acc[4] += c.x; acc[5] += c.y; acc[6] += d.x; acc[7] += d.y;
}
__device__ __forceinline__ uint4 hadd_u4(uint4 p, uint4 q) {
    uint4 r;
    *(__half2*)&r.x = __hadd2(*(__half2*)&p.x, *(__half2*)&q.x);
    *(__half2*)&r.y = __hadd2(*(__half2*)&p.y, *(__half2*)&q.y);
    *(__half2*)&r.z = __hadd2(*(__half2*)&p.z, *(__half2*)&q.z);
    *(__half2*)&r.w = __hadd2(*(__half2*)&p.w, *(__half2*)&q.w);
    return r;
}

// ---------------- v2e mean: fp16 gather, pairwise fp16 + fp32 accum ----------
__global__ __launch_bounds__(256) void k_v2e() {
    const int g    = threadIdx.x >> 5;
    const int lane = threadIdx.x & 31;
    const int e    = blockIdx.x * 8 + g;
    if (e >= NE) return;

    const int n = g_ecnt[e];
    const int m = min(n, CAPE);
    const int* __restrict__ sl = g_eslot + e * CAPE;
    const int off = lane * 8;

    float acc[8];
#pragma unroll
    for (int q = 0; q < 8; q++) acc[q] = 0.f;

    int i = 0;
    for (; i + 8 <= m; i += 8) {
        int4 i0 = *(const int4*)(sl + i);
        int4 i1 = *(const int4*)(sl + i + 4);
        uint4 u0 = *(const uint4*)(g_H + (size_t)i0.x * D + off);
        uint4 u1 = *(const uint4*)(g_H + (size_t)i0.y * D + off);
        uint4 u2 = *(const uint4*)(g_H + (size_t)i0.z * D + off);
        uint4 u3 = *(const uint4*)(g_H + (size_t)i0.w * D + off);
        uint4 u4 = *(const uint4*)(g_H + (size_t)i1.x * D + off);
        uint4 u5 = *(const uint4*)(g_H + (size_t)i1.y * D + off);
        uint4 u6 = *(const uint4*)(g_H + (size_t)i1.z * D + off);
        uint4 u7 = *(const uint4*)(g_H + (size_t)i1.w * D + off);
        acc_u4(acc, hadd_u4(u0, u1));
        acc_u4(acc, hadd_u4(u2, u3));
        acc_u4(acc, hadd_u4(u4, u5));
        acc_u4(acc, hadd_u4(u6, u7));
    }
    for (; i < m; i++) {
        int v = sl[i];
        acc_u4(acc, *(const uint4*)(g_H + (size_t)v * D + off));
    }
    float inv = 1.f / (float)max(n, 1);
    uint4 o;
    ((__half2*)&o.x)[0] = __floats2half2_rn(acc[0] * inv, acc[1] * inv);
    ((__half2*)&o.y)[0] = __floats2half2_rn(acc[2] * inv, acc[3] * inv);
    ((__half2*)&o.z)[0] = __floats2half2_rn(acc[4] * inv, acc[5] * inv);
    ((__half2*)&o.w)[0] = __floats2half2_rn(acc[6] * inv, acc[7] * inv);
    *(uint4*)(g_ef + (size_t)e * D + off) = o;
}

// ---------------- e2v mean + leaky relu, fp32 out ----------------------------
__global__ __launch_bounds__(256) void k_e2v(float* __restrict__ out) {
    const int g    = threadIdx.x >> 5;
    const int lane = threadIdx.x & 31;
    const int v    = blockIdx.x * 8 + g;
    if (v >= NV) return;

    const int n = g_vcnt[v];
    const int m = min(n, CAPV);
    const int* __restrict__ sl = g_vslot + v * CAPV;
    const int off = lane * 8;

    float acc[8];
#pragma unroll
    for (int q = 0; q < 8; q++) acc[q] = 0.f;

    int i = 0;
    for (; i + 8 <= m; i += 8) {
        int4 i0 = *(const int4*)(sl + i);
        int4 i1 = *(const int4*)(sl + i + 4);
        uint4 u0 = *(const uint4*)(g_ef + (size_t)i0.x * D + off);
        uint4 u1 = *(const uint4*)(g_ef + (size_t)i0.y * D + off);
        uint4 u2 = *(const uint4*)(g_ef + (size_t)i0.z * D + off);
        uint4 u3 = *(const uint4*)(g_ef + (size_t)i0.w * D + off);
        uint4 u4 = *(const uint4*)(g_ef + (size_t)i1.x * D + off);
        uint4 u5 = *(const uint4*)(g_ef + (size_t)i1.y * D + off);
        uint4 u6 = *(const uint4*)(g_ef + (size_t)i1.z * D + off);
        uint4 u7 = *(const uint4*)(g_ef + (size_t)i1.w * D + off);
        acc_u4(acc, hadd_u4(u0, u1));
        acc_u4(acc, hadd_u4(u2, u3));
        acc_u4(acc, hadd_u4(u4, u5));
        acc_u4(acc, hadd_u4(u6, u7));
    }
    if (i + 4 <= m) {
        int4 i0 = *(const int4*)(sl + i);
        uint4 u0 = *(const uint4*)(g_ef + (size_t)i0.x * D + off);
        uint4 u1 = *(const uint4*)(g_ef + (size_t)i0.y * D + off);
        uint4 u2 = *(const uint4*)(g_ef + (size_t)i0.z * D + off);
        uint4 u3 = *(const uint4*)(g_ef + (size_t)i0.w * D + off);
        acc_u4(acc, hadd_u4(u0, u1));
        acc_u4(acc, hadd_u4(u2, u3));
        i += 4;
    }
    for (; i < m; i++) {
        int e = sl[i];
        acc_u4(acc, *(const uint4*)(g_ef + (size_t)e * D + off));
    }
    float inv = 1.f / (float)max(n, 1);
    float4 o0, o1;
    float x;
    x = acc[0] * inv; o0.x = (x >= 0.f) ? x : 0.01f * x;
    x = acc[1] * inv; o0.y = (x >= 0.f) ? x : 0.01f * x;
    x = acc[2] * inv; o0.z = (x >= 0.f) ? x : 0.01f * x;
    x = acc[3] * inv; o0.w = (x >= 0.f) ? x : 0.01f * x;
    x = acc[4] * inv; o1.x = (x >= 0.f) ? x : 0.01f * x;
    x = acc[5] * inv; o1.y = (x >= 0.f) ? x : 0.01f * x;
    x = acc[6] * inv; o1.z = (x >= 0.f) ? x : 0.01f * x;
    x = acc[7] * inv; o1.w = (x >= 0.f) ? x : 0.01f * x;
    float* op = out + (size_t)v * D + off;
    *(float4*)(op)     = o0;
    *(float4*)(op + 4) = o1;
}

// ---------------- launch -----------------------------------------------------
extern "C" void kernel_launch(void* const* d_in, const int* in_sizes, int n_in,
                              void* d_out, int out_size) {
    const float* X     = (const float*)d_in[0];
    const float* W     = (const float*)d_in[1];
    const float* bias  = (const float*)d_in[2];
    const int*   v_idx = (const int*)d_in[3];
    const int*   e_idx = (const int*)d_in[4];
    float* out = (float*)d_out;

    cudaFuncSetAttribute(k_gemm, cudaFuncAttributeMaxDynamicSharedMemorySize,
                         SMEM_BYTES);

    k_init<<<256, 256>>>(W);
    k_build<<<(NP / 2 + 255) / 256, 256>>>(v_idx, e_idx);

    k_gemm<<<(NV + MT - 1) / MT, NTHR, SMEM_BYTES>>>(X, bias);

    k_v2e<<<(NE + 7) / 8, 256>>>();
    k_e2v<<<(NV + 7) / 8, 256>>>(out);
}

// round 15
// speedup vs baseline: 1.0494x; 1.0494x over previous
#include <cuda_runtime.h>
#include <cuda_bf16.h>
#include <cuda_fp16.h>
#include <cstdint>

#define NV 50000
#define NE 10000
#define NP 800000
#define D  256
#define CAPE 192
#define CAPV 64

// ---------------- device scratch (no runtime allocation allowed) -----------
// NOTE: g_ecnt / g_vcnt are zero-initialized at module load and SELF-CLEANED
// (reset to 0) by k_v2e / k_e2v at the end of every run, so every execution
// of kernel_launch starts with zeroed counters without an init kernel.
__device__ __half g_H[NV * D];                // 25.6 MB projected vertex features (fp16)
__device__ __half g_ef[NE * D];               // 5.1 MB  hyperedge features (fp16)
__device__ int    g_ecnt[NE];
__device__ int    g_vcnt[NV];
__device__ int    g_eslot[NE * CAPE];
__device__ int    g_vslot[NV * CAPV];
__device__ __half g_Wt16[D * D];              // W^T fp16 [n][k]

__device__ __forceinline__ uint32_t smem_u32(const void* p) {
    uint32_t a;
    asm("{ .reg .u64 t; cvta.to.shared.u64 t, %1; cvt.u32.u64 %0, t; }"
        : "=r"(a) : "l"(p));
    return a;
}

#define CP_ASYNC16(dst, src) \
    asm volatile("cp.async.cg.shared.global [%0], [%1], 16;" :: "r"(dst), "l"(src))
#define CP_COMMIT() asm volatile("cp.async.commit_group;" ::: "memory")
#define CP_WAIT0()  asm volatile("cp.async.wait_group 0;" ::: "memory")

// ---------------- build inverted slot lists + fp16-transpose W ---------------
__global__ void k_build(const int* __restrict__ v_idx,
                        const int* __restrict__ e_idx,
                        const float* __restrict__ W) {
    int i = blockIdx.x * blockDim.x + threadIdx.x;
    if (i < D * D) {                       // fold W transpose into this kernel
        int k = i >> 8, n = i & 255;
        g_Wt16[n * D + k] = __float2half_rn(W[k * D + n]);
    }
    if (i >= NP / 2) return;
    int2 vv = ((const int2*)v_idx)[i];
    int2 ee = ((const int2*)e_idx)[i];
#pragma unroll
    for (int t = 0; t < 2; t++) {
        int v = t ? vv.y : vv.x;
        int e = t ? ee.y : ee.x;
        int pe = atomicAdd(&g_ecnt[e], 1);
        if (pe < CAPE) g_eslot[e * CAPE + pe] = v;
        int pv = atomicAdd(&g_vcnt[v], 1);
        if (pv < CAPV) g_vslot[v * CAPV + pv] = e;
    }
}

// ---------------- fp16 GEMM (HMMA): H = X*W + b ------------------------------
// CTA tile 128x256, 512 threads / 16 warps (4 M x 4 N), warp tile 32x64.
#define MT 128
#define KC 64
#define NTHR 512
#define SM_W 0                       // 2 x 32 KB
#define SM_X (64 * 1024)             // 2 x 16 KB
#define SMEM_BYTES (96 * 1024)

extern __shared__ __align__(1024) char dynsm[];

__global__ __launch_bounds__(NTHR, 1) void k_gemm(const float* __restrict__ X,
                                                  const float* __restrict__ bias) {
    char* sm = dynsm;
    const int tid  = threadIdx.x;
    const int wid  = tid >> 5;
    const int lane = tid & 31;
    const int mbase = blockIdx.x * MT;
    const int wm = wid & 3;
    const int wn = wid >> 2;

    const uint32_t sm_u = smem_u32(sm);
    const uint32_t xorv = (uint32_t)(lane & 7) << 4;

    uint32_t aoff[2], boff[4];
#pragma unroll
    for (int t = 0; t < 2; t++)
        aoff[t] = (uint32_t)((wm * 32 + t * 16 + (lane & 15)) * 128 + (lane >> 4) * 16);
#pragma unroll
    for (int jj = 0; jj < 4; jj++)
        boff[jj] = (uint32_t)((wn * 64 + jj * 16 + (lane & 15)) * 128 + (lane >> 4) * 16);

    float acc[2][8][4];
#pragma unroll
    for (int t = 0; t < 2; t++)
#pragma unroll
        for (int j = 0; j < 8; j++)
#pragma unroll
            for (int q = 0; q < 4; q++) acc[t][j][q] = 0.f;

    float4 pf[4];

#define LOADX(c) do {                                                          \
    int kc = (c) * KC;                                                         \
    _Pragma("unroll")                                                          \
    for (int u2 = 0; u2 < 2; u2++) {                                           \
        int a = tid + u2 * NTHR;                                               \
        int r = a >> 3, sg = a & 7;                                            \
        int gr = mbase + r;                                                    \
        if (gr < NV) {                                                         \
            const float* p = X + (size_t)gr * D + kc + sg * 8;                 \
            pf[2 * u2]     = *(const float4*)(p);                              \
            pf[2 * u2 + 1] = *(const float4*)(p + 4);                          \
        } else {                                                               \
            pf[2 * u2] = pf[2 * u2 + 1] = make_float4(0.f, 0.f, 0.f, 0.f);     \
        }                                                                      \
    } } while (0)

#define CONVX(b) do {                                                          \
    _Pragma("unroll")                                                          \
    for (int u2 = 0; u2 < 2; u2++) {                                           \
        int a = tid + u2 * NTHR;                                               \
        int r = a >> 3, sg = a & 7;                                            \
        uint32_t off = (uint32_t)(r * 128 + sg * 16);                          \
        uint32_t sw  = off ^ (uint32_t)((r & 7) << 4);                         \
        __half2 h0 = __floats2half2_rn(pf[2*u2].x,   pf[2*u2].y);              \
        __half2 h1 = __floats2half2_rn(pf[2*u2].z,   pf[2*u2].w);              \
        __half2 h2 = __floats2half2_rn(pf[2*u2+1].x, pf[2*u2+1].y);            \
        __half2 h3 = __floats2half2_rn(pf[2*u2+1].z, pf[2*u2+1].w);            \
        char* xb = sm + SM_X + (b) * 16384;                                    \
        *(uint4*)(xb + sw) = make_uint4(*(uint32_t*)&h0, *(uint32_t*)&h1,      \
                                        *(uint32_t*)&h2, *(uint32_t*)&h3);     \
    } } while (0)

#define CPW(c, b) do {                                                         \
    int kc = (c) * KC;                                                         \
    _Pragma("unroll")                                                          \
    for (int u = 0; u < 4; u++) {                                              \
        int a = tid + u * NTHR;                                                \
        int n = a >> 3, sg = a & 7;                                            \
        const __half* srcp = g_Wt16 + (size_t)n * D + kc + sg * 8;             \
        uint32_t dst = sm_u + SM_W + (uint32_t)((b) * 32768) +                 \
                       (uint32_t)(n * 128) +                                   \
                       ((uint32_t)(sg * 16) ^ ((uint32_t)(n & 7) << 4));       \
        CP_ASYNC16(dst, srcp);                                                 \
    } } while (0)

    LOADX(0);
    CPW(0, 0);
    CP_COMMIT();
    CONVX(0);
    CP_WAIT0();
    __syncthreads();

    for (int c = 0; c < 4; c++) {
        if (c < 3) {
            LOADX(c + 1);
            CPW(c + 1, (c + 1) & 1);
            CP_COMMIT();
        }
        const uint32_t xbase = sm_u + SM_X + (uint32_t)((c & 1) * 16384);
        const uint32_t wbase = sm_u + SM_W + (uint32_t)((c & 1) * 32768);
#pragma unroll
        for (int s = 0; s < 4; s++) {
            const uint32_t kb = (uint32_t)(s * 32);
            uint32_t ar[2][4], br[4][4];
#pragma unroll
            for (int t = 0; t < 2; t++) {
                uint32_t ah = xbase + ((aoff[t] + kb) ^ xorv);
                asm volatile(
                    "ldmatrix.sync.aligned.m8n8.x4.shared.b16 {%0,%1,%2,%3}, [%4];"
                    : "=r"(ar[t][0]), "=r"(ar[t][1]), "=r"(ar[t][2]), "=r"(ar[t][3])
                    : "r"(ah));
            }
#pragma unroll
            for (int jj = 0; jj < 4; jj++) {
                uint32_t bh = wbase + ((boff[jj] + kb) ^ xorv);
                asm volatile(
                    "ldmatrix.sync.aligned.m8n8.x4.shared.b16 {%0,%1,%2,%3}, [%4];"
                    : "=r"(br[jj][0]), "=r"(br[jj][1]), "=r"(br[jj][2]), "=r"(br[jj][3])
                    : "r"(bh));
            }
#pragma unroll
            for (int t = 0; t < 2; t++)
#pragma unroll
                for (int j = 0; j < 8; j++) {
                    const int u = j >> 1, h = j & 1;
                    asm volatile(
                        "mma.sync.aligned.m16n8k16.row.col.f32.f16.f16.f32 "
                        "{%0,%1,%2,%3}, {%4,%5,%6,%7}, {%8,%9}, {%0,%1,%2,%3};"
                        : "+f"(acc[t][j][0]), "+f"(acc[t][j][1]),
                          "+f"(acc[t][j][2]), "+f"(acc[t][j][3])
                        : "r"(ar[t][0]), "r"(ar[t][1]), "r"(ar[t][2]), "r"(ar[t][3]),
                          "r"(br[u][h]), "r"(br[u][2 + h]));
                }
        }
        if (c < 3) {
            CONVX((c + 1) & 1);
            CP_WAIT0();
            __syncthreads();
        }
    }

    const int r0 = lane >> 2;
    const int c2 = (lane & 3) * 2;
#pragma unroll
    for (int t = 0; t < 2; t++) {
        int row = mbase + wm * 32 + t * 16 + r0;
#pragma unroll
        for (int j = 0; j < 8; j++) {
            int col = wn * 64 + j * 8 + c2;
            float2 bv = *(const float2*)(bias + col);
            if (row < NV) {
                __half2 o = __floats2half2_rn(acc[t][j][0] + bv.x,
                                              acc[t][j][1] + bv.y);
                *(__half2*)(g_H + (size_t)row * D + col) = o;
            }
            if (row + 8 < NV) {
                __half2 o = __floats2half2_rn(acc[t][j][2] + bv.x,
                                              acc[t][j][3] + bv.y);
                *(__half2*)(g_H + (size_t)(row + 8) * D + col) = o;
            }
        }
    }
#undef LOADX
#undef CONVX
#undef CPW
}

// ---- helpers ----------------------------------------------------------------
__device__ __forceinline__ void acc_u4(float* acc, uint4 u) {
    float2 a = __half22float2(*(__half2*)&u.x);
    float2 b = __half22float2(*(__half2*)&u.y);
    float2 c = __half22float2(*(__half2*)&u.z);
    float2 d = __half22float2(*(__half2*)&u.w);
    acc[0] += a.x; acc[1] += a.y; acc[2] += b.x; acc[3] += b.y;
    acc[4] += c.x; acc[5] += c.y; acc[6] += d.x; acc[7] += d.y;
}
__device__ __forceinline__ uint4 hadd_u4(uint4 p, uint4 q) {
    uint4 r;
    *(__half2*)&r.x = __hadd2(*(__half2*)&p.x, *(__half2*)&q.x);
    *(__half2*)&r.y = __hadd2(*(__half2*)&p.y, *(__half2*)&q.y);
    *(__half2*)&r.z = __hadd2(*(__half2*)&p.z, *(__half2*)&q.z);
    *(__half2*)&r.w = __hadd2(*(__half2*)&p.w, *(__half2*)&q.w);
    return r;
}

// ---------------- v2e mean: single resident wave, 2 edges per group ----------
// grid 625 x 256 threads: 5000 groups of 32 lanes, each handles edges e, e+5000.
__global__ __launch_bounds__(256) void k_v2e() {
    const int g    = threadIdx.x >> 5;
    const int lane = threadIdx.x & 31;
    const int off  = lane * 8;

    for (int e = blockIdx.x * 8 + g; e < NE; e += 5000) {
        const int n = g_ecnt[e];
        const int m = min(n, CAPE);
        const int* __restrict__ sl = g_eslot + e * CAPE;

        float acc[8];
#pragma unroll
        for (int q = 0; q < 8; q++) acc[q] = 0.f;

        int i = 0;
        for (; i + 8 <= m; i += 8) {
            int4 i0 = *(const int4*)(sl + i);
            int4 i1 = *(const int4*)(sl + i + 4);
            uint4 u0 = *(const uint4*)(g_H + (size_t)i0.x * D + off);
            uint4 u1 = *(const uint4*)(g_H + (size_t)i0.y * D + off);
            uint4 u2 = *(const uint4*)(g_H + (size_t)i0.z * D + off);
            uint4 u3 = *(const uint4*)(g_H + (size_t)i0.w * D + off);
            uint4 u4 = *(const uint4*)(g_H + (size_t)i1.x * D + off);
            uint4 u5 = *(const uint4*)(g_H + (size_t)i1.y * D + off);
            uint4 u6 = *(const uint4*)(g_H + (size_t)i1.z * D + off);
            uint4 u7 = *(const uint4*)(g_H + (size_t)i1.w * D + off);
            acc_u4(acc, hadd_u4(u0, u1));
            acc_u4(acc, hadd_u4(u2, u3));
            acc_u4(acc, hadd_u4(u4, u5));
            acc_u4(acc, hadd_u4(u6, u7));
        }
        for (; i < m; i++) {
            int v = sl[i];
            acc_u4(acc, *(const uint4*)(g_H + (size_t)v * D + off));
        }
        float inv = 1.f / (float)max(n, 1);
        uint4 o;
        ((__half2*)&o.x)[0] = __floats2half2_rn(acc[0] * inv, acc[1] * inv);
        ((__half2*)&o.y)[0] = __floats2half2_rn(acc[2] * inv, acc[3] * inv);
        ((__half2*)&o.z)[0] = __floats2half2_rn(acc[4] * inv, acc[5] * inv);
        ((__half2*)&o.w)[0] = __floats2half2_rn(acc[6] * inv, acc[7] * inv);
        *(uint4*)(g_ef + (size_t)e * D + off) = o;

        __syncwarp();                       // all lanes done reading g_ecnt[e]
        if (lane == 0) g_ecnt[e] = 0;       // self-clean for next run
    }
}

// ---------------- e2v mean + leaky relu: resident wave, looped vertices ------
// grid 782 x 256 threads: 6256 groups, each loops v, v+6256, ... (~8 vertices)
__global__ __launch_bounds__(256) void k_e2v(float* __restrict__ out) {
    const int g    = threadIdx.x >> 5;
    const int lane = threadIdx.x & 31;
    const int off  = lane * 8;

    for (int v = blockIdx.x * 8 + g; v < NV; v += 6256) {
        const int n = g_vcnt[v];
        const int m = min(n, CAPV);
        const int* __restrict__ sl = g_vslot + v * CAPV;

        float acc[8];
#pragma unroll
        for (int q = 0; q < 8; q++) acc[q] = 0.f;

        int i = 0;
        for (; i + 8 <= m; i += 8) {
            int4 i0 = *(const int4*)(sl + i);
            int4 i1 = *(const int4*)(sl + i + 4);
            uint4 u0 = *(const uint4*)(g_ef + (size_t)i0.x * D + off);
            uint4 u1 = *(const uint4*)(g_ef + (size_t)i0.y * D + off);
            uint4 u2 = *(const uint4*)(g_ef + (size_t)i0.z * D + off);
            uint4 u3 = *(const uint4*)(g_ef + (size_t)i0.w * D + off);
            uint4 u4 = *(const uint4*)(g_ef + (size_t)i1.x * D + off);
            uint4 u5 = *(const uint4*)(g_ef + (size_t)i1.y * D + off);
            uint4 u6 = *(const uint4*)(g_ef + (size_t)i1.z * D + off);
            uint4 u7 = *(const uint4*)(g_ef + (size_t)i1.w * D + off);
            acc_u4(acc, hadd_u4(u0, u1));
            acc_u4(acc, hadd_u4(u2, u3));
            acc_u4(acc, hadd_u4(u4, u5));
            acc_u4(acc, hadd_u4(u6, u7));
        }
        if (i + 4 <= m) {
            int4 i0 = *(const int4*)(sl + i);
            uint4 u0 = *(const uint4*)(g_ef + (size_t)i0.x * D + off);
            uint4 u1 = *(const uint4*)(g_ef + (size_t)i0.y * D + off);
            uint4 u2 = *(const uint4*)(g_ef + (size_t)i0.z * D + off);
            uint4 u3 = *(const uint4*)(g_ef + (size_t)i0.w * D + off);
            acc_u4(acc, hadd_u4(u0, u1));
            acc_u4(acc, hadd_u4(u2, u3));
            i += 4;
        }
        for (; i < m; i++) {
            int e = sl[i];
            acc_u4(acc, *(const uint4*)(g_ef + (size_t)e * D + off));
        }
        float inv = 1.f / (float)max(n, 1);
        float4 o0, o1;
        float x;
        x = acc[0] * inv; o0.x = (x >= 0.f) ? x : 0.01f * x;
        x = acc[1] * inv; o0.y = (x >= 0.f) ? x : 0.01f * x;
        x = acc[2] * inv; o0.z = (x >= 0.f) ? x : 0.01f * x;
        x = acc[3] * inv; o0.w = (x >= 0.f) ? x : 0.01f * x;
        x = acc[4] * inv; o1.x = (x >= 0.f) ? x : 0.01f * x;
        x = acc[5] * inv; o1.y = (x >= 0.f) ? x : 0.01f * x;
        x = acc[6] * inv; o1.z = (x >= 0.f) ? x : 0.01f * x;
        x = acc[7] * inv; o1.w = (x >= 0.f) ? x : 0.01f * x;
        float* op = out + (size_t)v * D + off;
        *(float4*)(op)     = o0;
        *(float4*)(op + 4) = o1;

        __syncwarp();                       // all lanes done reading g_vcnt[v]
        if (lane == 0) g_vcnt[v] = 0;       // self-clean for next run
    }
}

// ---------------- launch -----------------------------------------------------
extern "C" void kernel_launch(void* const* d_in, const int* in_sizes, int n_in,
                              void* d_out, int out_size) {
    const float* X     = (const float*)d_in[0];
    const float* W     = (const float*)d_in[1];
    const float* bias  = (const float*)d_in[2];
    const int*   v_idx = (const int*)d_in[3];
    const int*   e_idx = (const int*)d_in[4];
    float* out = (float*)d_out;

    cudaFuncSetAttribute(k_gemm, cudaFuncAttributeMaxDynamicSharedMemorySize,
                         SMEM_BYTES);

    k_build<<<(NP / 2 + 255) / 256, 256>>>(v_idx, e_idx, W);

    k_gemm<<<(NV + MT - 1) / MT, NTHR, SMEM_BYTES>>>(X, bias);

    k_v2e<<<625, 256>>>();
    k_e2v<<<782, 256>>>(out);
}

// round 17
// speedup vs baseline: 1.0643x; 1.0142x over previous
#include <cuda_runtime.h>
#include <cuda_bf16.h>
#include <cuda_fp16.h>
#include <cstdint>

#define NV 50000
#define NE 10000
#define NP 800000
#define D  256
#define CAPE 192
#define CAPV 64

// ---------------- device scratch (no runtime allocation allowed) -----------
// g_ecnt / g_vcnt are zero-initialized at module load and SELF-CLEANED by
// k_v2e / k_e2v after consumption, so every run starts with zeroed counters.
__device__ __half g_H[NV * D];                // 25.6 MB projected vertex features (fp16)
__device__ __half g_ef[NE * D];               // 5.1 MB  hyperedge features (fp16)
__device__ int    g_ecnt[NE];
__device__ int    g_vcnt[NV];
__device__ int    g_eslot[NE * CAPE];
__device__ int    g_vslot[NV * CAPV];
__device__ __half g_Wt16[D * D];              // W^T fp16 [n][k]

__device__ __forceinline__ uint32_t smem_u32(const void* p) {
    uint32_t a;
    asm("{ .reg .u64 t; cvta.to.shared.u64 t, %1; cvt.u32.u64 %0, t; }"
        : "=r"(a) : "l"(p));
    return a;
}

#define CP_ASYNC16(dst, src) \
    asm volatile("cp.async.cg.shared.global [%0], [%1], 16;" :: "r"(dst), "l"(src))
#define CP_COMMIT() asm volatile("cp.async.commit_group;" ::: "memory")
#define CP_WAIT0()  asm volatile("cp.async.wait_group 0;" ::: "memory")

// ---------------- build inverted slot lists + fp16-transpose W ---------------
__global__ void k_build(const int* __restrict__ v_idx,
                        const int* __restrict__ e_idx,
                        const float* __restrict__ W) {
    int i = blockIdx.x * blockDim.x + threadIdx.x;
    if (i < D * D) {
        int k = i >> 8, n = i & 255;
        g_Wt16[n * D + k] = __float2half_rn(W[k * D + n]);
    }
    if (i >= NP / 2) return;
    int2 vv = ((const int2*)v_idx)[i];
    int2 ee = ((const int2*)e_idx)[i];
#pragma unroll
    for (int t = 0; t < 2; t++) {
        int v = t ? vv.y : vv.x;
        int e = t ? ee.y : ee.x;
        int pe = atomicAdd(&g_ecnt[e], 1);
        if (pe < CAPE) g_eslot[e * CAPE + pe] = v;
        int pv = atomicAdd(&g_vcnt[v], 1);
        if (pv < CAPV) g_vslot[v * CAPV + pv] = e;
    }
}

// ---------------- fp16 GEMM (HMMA): H = X*W + b ------------------------------
// CTA tile 128x256, 512 threads / 16 warps (4 M x 4 N), warp tile 32x64.
#define MT 128
#define KC 64
#define NTHR 512
#define SM_W 0                       // 2 x 32 KB
#define SM_X (64 * 1024)             // 2 x 16 KB
#define SMEM_BYTES (96 * 1024)

extern __shared__ __align__(1024) char dynsm[];

__global__ __launch_bounds__(NTHR, 1) void k_gemm(const float* __restrict__ X,
                                                  const float* __restrict__ bias) {
    char* sm = dynsm;
    const int tid  = threadIdx.x;
    const int wid  = tid >> 5;
    const int lane = tid & 31;
    const int mbase = blockIdx.x * MT;
    const int wm = wid & 3;
    const int wn = wid >> 2;

    const uint32_t sm_u = smem_u32(sm);
    const uint32_t xorv = (uint32_t)(lane & 7) << 4;

    uint32_t aoff[2], boff[4];
#pragma unroll
    for (int t = 0; t < 2; t++)
        aoff[t] = (uint32_t)((wm * 32 + t * 16 + (lane & 15)) * 128 + (lane >> 4) * 16);
#pragma unroll
    for (int jj = 0; jj < 4; jj++)
        boff[jj] = (uint32_t)((wn * 64 + jj * 16 + (lane & 15)) * 128 + (lane >> 4) * 16);

    float acc[2][8][4];
#pragma unroll
    for (int t = 0; t < 2; t++)
#pragma unroll
        for (int j = 0; j < 8; j++)
#pragma unroll
            for (int q = 0; q < 4; q++) acc[t][j][q] = 0.f;

    float4 pf[4];

#define LOADX(c) do {                                                          \
    int kc = (c) * KC;                                                         \
    _Pragma("unroll")                                                          \
    for (int u2 = 0; u2 < 2; u2++) {                                           \
        int a = tid + u2 * NTHR;                                               \
        int r = a >> 3, sg = a & 7;                                            \
        int gr = mbase + r;                                                    \
        if (gr < NV) {                                                         \
            const float* p = X + (size_t)gr * D + kc + sg * 8;                 \
            pf[2 * u2]     = *(const float4*)(p);                              \
            pf[2 * u2 + 1] = *(const float4*)(p + 4);                          \
        } else {                                                               \
            pf[2 * u2] = pf[2 * u2 + 1] = make_float4(0.f, 0.f, 0.f, 0.f);     \
        }                                                                      \
    } } while (0)

#define CONVX(b) do {                                                          \
    _Pragma("unroll")                                                          \
    for (int u2 = 0; u2 < 2; u2++) {                                           \
        int a = tid + u2 * NTHR;                                               \
        int r = a >> 3, sg = a & 7;                                            \
        uint32_t off = (uint32_t)(r * 128 + sg * 16);                          \
        uint32_t sw  = off ^ (uint32_t)((r & 7) << 4);                         \
        __half2 h0 = __floats2half2_rn(pf[2*u2].x,   pf[2*u2].y);              \
        __half2 h1 = __floats2half2_rn(pf[2*u2].z,   pf[2*u2].w);              \
        __half2 h2 = __floats2half2_rn(pf[2*u2+1].x, pf[2*u2+1].y);            \
        __half2 h3 = __floats2half2_rn(pf[2*u2+1].z, pf[2*u2+1].w);            \
        char* xb = sm + SM_X + (b) * 16384;                                    \
        *(uint4*)(xb + sw) = make_uint4(*(uint32_t*)&h0, *(uint32_t*)&h1,      \
                                        *(uint32_t*)&h2, *(uint32_t*)&h3);     \
    } } while (0)

#define CPW(c, b) do {                                                         \
    int kc = (c) * KC;                                                         \
    _Pragma("unroll")                                                          \
    for (int u = 0; u < 4; u++) {                                              \
        int a = tid + u * NTHR;                                                \
        int n = a >> 3, sg = a & 7;                                            \
        const __half* srcp = g_Wt16 + (size_t)n * D + kc + sg * 8;             \
        uint32_t dst = sm_u + SM_W + (uint32_t)((b) * 32768) +                 \
                       (uint32_t)(n * 128) +                                   \
                       ((uint32_t)(sg * 16) ^ ((uint32_t)(n & 7) << 4));       \
        CP_ASYNC16(dst, srcp);                                                 \
    } } while (0)

    LOADX(0);
    CPW(0, 0);
    CP_COMMIT();
    CONVX(0);
    CP_WAIT0();
    __syncthreads();

    for (int c = 0; c < 4; c++) {
        if (c < 3) {
            LOADX(c + 1);
            CPW(c + 1, (c + 1) & 1);
            CP_COMMIT();
        }
        const uint32_t xbase = sm_u + SM_X + (uint32_t)((c & 1) * 16384);
        const uint32_t wbase = sm_u + SM_W + (uint32_t)((c & 1) * 32768);
#pragma unroll
        for (int s = 0; s < 4; s++) {
            const uint32_t kb = (uint32_t)(s * 32);
            uint32_t ar[2][4], br[4][4];
#pragma unroll
            for (int t = 0; t < 2; t++) {
                uint32_t ah = xbase + ((aoff[t] + kb) ^ xorv);
                asm volatile(
                    "ldmatrix.sync.aligned.m8n8.x4.shared.b16 {%0,%1,%2,%3}, [%4];"
                    : "=r"(ar[t][0]), "=r"(ar[t][1]), "=r"(ar[t][2]), "=r"(ar[t][3])
                    : "r"(ah));
            }
#pragma unroll
            for (int jj = 0; jj < 4; jj++) {
                uint32_t bh = wbase + ((boff[jj] + kb) ^ xorv);
                asm volatile(
                    "ldmatrix.sync.aligned.m8n8.x4.shared.b16 {%0,%1,%2,%3}, [%4];"
                    : "=r"(br[jj][0]), "=r"(br[jj][1]), "=r"(br[jj][2]), "=r"(br[jj][3])
                    : "r"(bh));
            }
#pragma unroll
            for (int t = 0; t < 2; t++)
#pragma unroll
                for (int j = 0; j < 8; j++) {
                    const int u = j >> 1, h = j & 1;
                    asm volatile(
                        "mma.sync.aligned.m16n8k16.row.col.f32.f16.f16.f32 "
                        "{%0,%1,%2,%3}, {%4,%5,%6,%7}, {%8,%9}, {%0,%1,%2,%3};"
                        : "+f"(acc[t][j][0]), "+f"(acc[t][j][1]),
                          "+f"(acc[t][j][2]), "+f"(acc[t][j][3])
                        : "r"(ar[t][0]), "r"(ar[t][1]), "r"(ar[t][2]), "r"(ar[t][3]),
                          "r"(br[u][h]), "r"(br[u][2 + h]));
                }
        }
        if (c < 3) {
            CONVX((c + 1) & 1);
            CP_WAIT0();
            __syncthreads();
        }
    }

    const int r0 = lane >> 2;
    const int c2 = (lane & 3) * 2;
#pragma unroll
    for (int t = 0; t < 2; t++) {
        int row = mbase + wm * 32 + t * 16 + r0;
#pragma unroll
        for (int j = 0; j < 8; j++) {
            int col = wn * 64 + j * 8 + c2;
            float2 bv = *(const float2*)(bias + col);
            if (row < NV) {
                __half2 o = __floats2half2_rn(acc[t][j][0] + bv.x,
                                              acc[t][j][1] + bv.y);
                *(__half2*)(g_H + (size_t)row * D + col) = o;
            }
            if (row + 8 < NV) {
                __half2 o = __floats2half2_rn(acc[t][j][2] + bv.x,
                                              acc[t][j][3] + bv.y);
                *(__half2*)(g_H + (size_t)(row + 8) * D + col) = o;
            }
        }
    }
#undef LOADX
#undef CONVX
#undef CPW
}

// ---- helpers ----------------------------------------------------------------
__device__ __forceinline__ void acc_u4(float* acc, uint4 u) {
    float2 a = __half22float2(*(__half2*)&u.x);
    float2 b = __half22float2(*(__half2*)&u.y);
    float2 c = __half22float2(*(__half2*)&u.z);
    float2 d = __half22float2(*(__half2*)&u.w);
    acc[0] += a.x; acc[1] += a.y; acc[2] += b.x; acc[3] += b.y;
    acc[4] += c.x; acc[5] += c.y; acc[6] += d.x; acc[7] += d.y;
}
__device__ __forceinline__ uint4 hadd_u4(uint4 p, uint4 q) {
    uint4 r;
    *(__half2*)&r.x = __hadd2(*(__half2*)&p.x, *(__half2*)&q.x);
    *(__half2*)&r.y = __hadd2(*(__half2*)&p.y, *(__half2*)&q.y);
    *(__half2*)&r.z = __hadd2(*(__half2*)&p.z, *(__half2*)&q.z);
    *(__half2*)&r.w = __hadd2(*(__half2*)&p.w, *(__half2*)&q.w);
    return r;
}

// ---------------- v2e mean: flat grid, 2-level fp16 tree + fp32 accum --------
// grid 1250 x 256: 8 edges per block, 32 lanes per edge, lane owns 8 dims.
__global__ __launch_bounds__(256) void k_v2e() {
    const int g    = threadIdx.x >> 5;
    const int lane = threadIdx.x & 31;
    const int e    = blockIdx.x * 8 + g;
    if (e >= NE) return;

    const int n = g_ecnt[e];
    const int m = min(n, CAPE);
    const int* __restrict__ sl = g_eslot + e * CAPE;
    const int off = lane * 8;

    float acc[8];
#pragma unroll
    for (int q = 0; q < 8; q++) acc[q] = 0.f;

    int i = 0;
    for (; i + 8 <= m; i += 8) {
        int4 i0 = *(const int4*)(sl + i);
        int4 i1 = *(const int4*)(sl + i + 4);
        uint4 u0 = *(const uint4*)(g_H + (size_t)i0.x * D + off);
        uint4 u1 = *(const uint4*)(g_H + (size_t)i0.y * D + off);
        uint4 u2 = *(const uint4*)(g_H + (size_t)i0.z * D + off);
        uint4 u3 = *(const uint4*)(g_H + (size_t)i0.w * D + off);
        uint4 u4 = *(const uint4*)(g_H + (size_t)i1.x * D + off);
        uint4 u5 = *(const uint4*)(g_H + (size_t)i1.y * D + off);
        uint4 u6 = *(const uint4*)(g_H + (size_t)i1.z * D + off);
        uint4 u7 = *(const uint4*)(g_H + (size_t)i1.w * D + off);
        acc_u4(acc, hadd_u4(hadd_u4(u0, u1), hadd_u4(u2, u3)));
        acc_u4(acc, hadd_u4(hadd_u4(u4, u5), hadd_u4(u6, u7)));
    }
    if (i + 4 <= m) {
        int4 i0 = *(const int4*)(sl + i);
        uint4 u0 = *(const uint4*)(g_H + (size_t)i0.x * D + off);
        uint4 u1 = *(const uint4*)(g_H + (size_t)i0.y * D + off);
        uint4 u2 = *(const uint4*)(g_H + (size_t)i0.z * D + off);
        uint4 u3 = *(const uint4*)(g_H + (size_t)i0.w * D + off);
        acc_u4(acc, hadd_u4(u0, u1));
        acc_u4(acc, hadd_u4(u2, u3));
        i += 4;
    }
    for (; i < m; i++) {
        int v = sl[i];
        acc_u4(acc, *(const uint4*)(g_H + (size_t)v * D + off));
    }
    float inv = 1.f / (float)max(n, 1);
    uint4 o;
    ((__half2*)&o.x)[0] = __floats2half2_rn(acc[0] * inv, acc[1] * inv);
    ((__half2*)&o.y)[0] = __floats2half2_rn(acc[2] * inv, acc[3] * inv);
    ((__half2*)&o.z)[0] = __floats2half2_rn(acc[4] * inv, acc[5] * inv);
    ((__half2*)&o.w)[0] = __floats2half2_rn(acc[6] * inv, acc[7] * inv);
    *(uint4*)(g_ef + (size_t)e * D + off) = o;

    __syncwarp();                       // all lanes done reading g_ecnt[e]
    if (lane == 0) g_ecnt[e] = 0;       // self-clean for next run
}

// ---------------- e2v mean + leaky relu: flat grid, 2-level fp16 tree --------
// grid 6250 x 256: 8 vertices per block, 32 lanes per vertex.
__global__ __launch_bounds__(256) void k_e2v(float* __restrict__ out) {
    const int g    = threadIdx.x >> 5;
    const int lane = threadIdx.x & 31;
    const int v    = blockIdx.x * 8 + g;
    if (v >= NV) return;

    const int n = g_vcnt[v];
    const int m = min(n, CAPV);
    const int* __restrict__ sl = g_vslot + v * CAPV;
    const int off = lane * 8;

    float acc[8];
#pragma unroll
    for (int q = 0; q < 8; q++) acc[q] = 0.f;

    int i = 0;
    for (; i + 8 <= m; i += 8) {
        int4 i0 = *(const int4*)(sl + i);
        int4 i1 = *(const int4*)(sl + i + 4);
        uint4 u0 = *(const uint4*)(g_ef + (size_t)i0.x * D + off);
        uint4 u1 = *(const uint4*)(g_ef + (size_t)i0.y * D + off);
        uint4 u2 = *(const uint4*)(g_ef + (size_t)i0.z * D + off);
        uint4 u3 = *(const uint4*)(g_ef + (size_t)i0.w * D + off);
        uint4 u4 = *(const uint4*)(g_ef + (size_t)i1.x * D + off);
        uint4 u5 = *(const uint4*)(g_ef + (size_t)i1.y * D + off);
        uint4 u6 = *(const uint4*)(g_ef + (size_t)i1.z * D + off);
        uint4 u7 = *(const uint4*)(g_ef + (size_t)i1.w * D + off);
        acc_u4(acc, hadd_u4(hadd_u4(u0, u1), hadd_u4(u2, u3)));
        acc_u4(acc, hadd_u4(hadd_u4(u4, u5), hadd_u4(u6, u7)));
    }
    if (i + 4 <= m) {
        int4 i0 = *(const int4*)(sl + i);
        uint4 u0 = *(const uint4*)(g_ef + (size_t)i0.x * D + off);
        uint4 u1 = *(const uint4*)(g_ef + (size_t)i0.y * D + off);
        uint4 u2 = *(const uint4*)(g_ef + (size_t)i0.z * D + off);
        uint4 u3 = *(const uint4*)(g_ef + (size_t)i0.w * D + off);
        acc_u4(acc, hadd_u4(u0, u1));
        acc_u4(acc, hadd_u4(u2, u3));
        i += 4;
    }
    for (; i < m; i++) {
        int e = sl[i];
        acc_u4(acc, *(const uint4*)(g_ef + (size_t)e * D + off));
    }
    float inv = 1.f / (float)max(n, 1);
    float4 o0, o1;
    float x;
    x = acc[0] * inv; o0.x = (x >= 0.f) ? x : 0.01f * x;
    x = acc[1] * inv; o0.y = (x >= 0.f) ? x : 0.01f * x;
    x = acc[2] * inv; o0.z = (x >= 0.f) ? x : 0.01f * x;
    x = acc[3] * inv; o0.w = (x >= 0.f) ? x : 0.01f * x;
    x = acc[4] * inv; o1.x = (x >= 0.f) ? x : 0.01f * x;
    x = acc[5] * inv; o1.y = (x >= 0.f) ? x : 0.01f * x;
    x = acc[6] * inv; o1.z = (x >= 0.f) ? x : 0.01f * x;
    x = acc[7] * inv; o1.w = (x >= 0.f) ? x : 0.01f * x;
    float* op = out + (size_t)v * D + off;
    *(float4*)(op)     = o0;
    *(float4*)(op + 4) = o1;

    __syncwarp();                       // all lanes done reading g_vcnt[v]
    if (lane == 0) g_vcnt[v] = 0;       // self-clean for next run
}

// ---------------- launch -----------------------------------------------------
extern "C" void kernel_launch(void* const* d_in, const int* in_sizes, int n_in,
                              void* d_out, int out_size) {
    const float* X     = (const float*)d_in[0];
    const float* W     = (const float*)d_in[1];
    const float* bias  = (const float*)d_in[2];
    const int*   v_idx = (const int*)d_in[3];
    const int*   e_idx = (const int*)d_in[4];
    float* out = (float*)d_out;

    cudaFuncSetAttribute(k_gemm, cudaFuncAttributeMaxDynamicSharedMemorySize,
                         SMEM_BYTES);

    k_build<<<(NP / 2 + 255) / 256, 256>>>(v_idx, e_idx, W);

    k_gemm<<<(NV + MT - 1) / MT, NTHR, SMEM_BYTES>>>(X, bias);

    k_v2e<<<(NE + 7) / 8, 256>>>();
    k_e2v<<<(NV + 7) / 8, 256>>>(out);
}